// round 14
// baseline (speedup 1.0000x reference)
#include <cuda_runtime.h>
#include <cuda_bf16.h>
#include <math.h>
#include <cstdint>

// R14: 16-warp GEMM CTAs. Evidence across R5/R8/R11/R13: every 8-warp variant
// pins at issue 14-18% / tensor 18-30% regardless of sync strategy or tile
// scheduling -> warp-starved (2 eligible warps/SMSP can't cover ldmatrix->MMA
// chains). This round: 512 threads / 16 warps (4/SMSP), warp tile 16x64,
// BM=BN=128, A staged warp-private (duplicated per n-half so warps stay fully
// decoupled; single buffer per warp, __syncwarp only), B resident full-K.
// acc drops to 32 regs/thread (R13's 255-reg spill cliff avoided).
// Persistence (R13 regression) reverted.

// ---------------------------------------------------------------------------
// Problem constants (fixed by the dataset's setup_inputs)
// ---------------------------------------------------------------------------
constexpr int B_  = 8;
constexpr int Q_  = 2048;
constexpr int D_  = 256;
constexpr int Hh  = 100;
constexpr int Ww  = 100;
constexpr int HW  = Hh * Ww;       // 10000
constexpr int NH  = 8;
constexpr int NP  = 4;
constexpr int DH  = D_ / NH;       // 32
constexpr int BQ  = B_ * Q_;       // 16384
constexpr int PN  = 128;           // padded projection width (64 off + 32 attn + pad)

// Scratch (allocation-free rule: __device__ globals)
__device__ float         g_values[(size_t)B_ * HW * D_];   // 81.9 MB
__device__ float         g_result[(size_t)BQ * D_];        // 16.8 MB
__device__ float         g_proj[(size_t)BQ * PN];          // 8.4 MB
__device__ __nv_bfloat16 g_WvalT_hi[D_ * D_], g_WvalT_lo[D_ * D_];
__device__ __nv_bfloat16 g_WoutT_hi[D_ * D_], g_WoutT_lo[D_ * D_];
__device__ __nv_bfloat16 g_Wcomb_hi[PN * D_], g_Wcomb_lo[PN * D_];
__device__ float         g_bias_comb[PN];

// ---------------------------------------------------------------------------
// Helpers
// ---------------------------------------------------------------------------
__device__ __forceinline__ uint32_t smem_u32(const void* p) {
    uint32_t a;
    asm("{ .reg .u64 t; cvta.to.shared.u64 t, %1; cvt.u32.u64 %0, t; }" : "=r"(a) : "l"(p));
    return a;
}
// swizzle for 128B-row layouts: 16B-unit ^= (row & 7)
__device__ __forceinline__ uint32_t swz128(uint32_t off) { return off ^ ((off >> 3) & 0x70); }
// swizzle for 512B-row layouts
__device__ __forceinline__ uint32_t swz512(uint32_t off) { return off ^ ((off >> 5) & 0x70); }

__device__ __forceinline__ uint32_t pack2bf(float a, float b) {   // a -> low half
    __nv_bfloat162 t = __floats2bfloat162_rn(a, b);
    return *reinterpret_cast<uint32_t*>(&t);
}
__device__ __forceinline__ void bf_split(float x, float& hf, float& lf) {
    __nv_bfloat16 h = __float2bfloat16_rn(x);
    hf = __bfloat162float(h);
    lf = x - hf;
}

__device__ __forceinline__ void ldm_x4(uint32_t* r, uint32_t addr) {
    asm volatile("ldmatrix.sync.aligned.m8n8.x4.shared.b16 {%0,%1,%2,%3}, [%4];"
        : "=r"(r[0]), "=r"(r[1]), "=r"(r[2]), "=r"(r[3]) : "r"(addr));
}
__device__ __forceinline__ void mma_bf16(float* d, const uint32_t* a, const uint32_t* b) {
    asm volatile("mma.sync.aligned.m16n8k16.row.col.f32.bf16.bf16.f32 "
        "{%0,%1,%2,%3}, {%4,%5,%6,%7}, {%8,%9}, {%0,%1,%2,%3};"
        : "+f"(d[0]), "+f"(d[1]), "+f"(d[2]), "+f"(d[3])
        : "r"(a[0]), "r"(a[1]), "r"(a[2]), "r"(a[3]), "r"(b[0]), "r"(b[1]));
}

// ---------------------------------------------------------------------------
// bf16x3 GEMM via mma.sync: C[M,N] = A[M,256] @ (Bhi+Blo)[N,256]^T + bias
//   512 threads / 16 warps. BM=128, BN=128, warp tile 16x64:
//   warp w -> rows (w&7)*16, cols (w>>3)*64.
//   B (hi+lo, full K=256) resident in SMEM (swz512), loaded once behind the
//   single prologue __syncthreads. A staged warp-private per 64-float chunk
//   (each warp stages its own 16 rows -> duplicated across the two n-halves),
//   single buffer per warp, __syncwarp-only ordering.
// SMEM: BH 64KB | BL 64KB | A: 16 warps x (hi 2KB + lo 2KB) = 64KB -> 192KB.
// ---------------------------------------------------------------------------
constexpr int SB_BH = 0;
constexpr int SB_BL = 65536;
constexpr int SB_A  = 131072;          // + w*4096 ; lo at +2048
constexpr int SMEM_GEMM = 196608;

__global__ __launch_bounds__(512, 1)
void gemm_bf16x3(const float* __restrict__ A,
                 const __nv_bfloat16* __restrict__ Bhi,
                 const __nv_bfloat16* __restrict__ Blo,
                 const float* __restrict__ bias,
                 float* __restrict__ C, int N)
{
    extern __shared__ char smem[];
    const uint32_t sb = smem_u32(smem);
    const int tid  = threadIdx.x;
    const int bm   = blockIdx.x * 128;
    const int bn   = blockIdx.y * 128;
    const int w    = tid >> 5;
    const int lane = tid & 31;
    const int wm   = (w & 7) * 16;           // this warp's 16 M-rows (in-tile)
    const int wn   = (w >> 3) * 64;          // this warp's 64 N-cols (in-tile)

    // Warp-private A staging: 32 lanes cover 16 rows x 2 halves (32 floats/lane)
    const int lr    = lane >> 1;             // local row 0..15
    const int ahalf = lane & 1;              // 0 or 1 (32-float half)
    const float* Abase = A + (size_t)(bm + wm + lr) * 256 + ahalf * 32;
    const uint32_t aWarp = sb + SB_A + w * 4096;   // hi @0, lo @+2048

    float acc[8][4];
    #pragma unroll
    for (int j = 0; j < 8; j++)
        #pragma unroll
        for (int k = 0; k < 4; k++) acc[j][k] = 0.f;

    // ---- Prologue: load full B (hi+lo, [128 rows][512B]) into resident SMEM ----
    {
        const char* BhB = (const char*)(Bhi + (size_t)bn * 256);
        const char* BlB = (const char*)(Blo + (size_t)bn * 256);
        #pragma unroll
        for (int i = 0; i < 8; i++) {
            int u = i * 512 + tid;                 // 4096 16B-units per half
            uint32_t off = (uint32_t)u * 16;
            uint4 hv = *(const uint4*)(BhB + off);
            uint4 lv = *(const uint4*)(BlB + off);
            uint32_t so = swz512(off);
            *(uint4*)(smem + SB_BH + so) = hv;
            *(uint4*)(smem + SB_BL + so) = lv;
        }
    }
    __syncthreads();   // only full-CTA sync in the kernel

    float4 a_st[8];
    auto stageA = [&](int c) {
        #pragma unroll
        for (int j = 0; j < 8; j++)
            a_st[j] = *(const float4*)(Abase + c * 64 + j * 4);
    };
    auto cvtstoreA = [&]() {
        char* bp = smem + SB_A + w * 4096;
        #pragma unroll
        for (int j = 0; j < 4; j++) {
            float4 v0 = a_st[2 * j], v1 = a_st[2 * j + 1];
            float h0,l0,h1,l1,h2,l2,h3,l3,h4,l4,h5,l5,h6,l6,h7,l7;
            bf_split(v0.x,h0,l0); bf_split(v0.y,h1,l1); bf_split(v0.z,h2,l2); bf_split(v0.w,h3,l3);
            bf_split(v1.x,h4,l4); bf_split(v1.y,h5,l5); bf_split(v1.z,h6,l6); bf_split(v1.w,h7,l7);
            uint4 hv = { pack2bf(h0,h1), pack2bf(h2,h3), pack2bf(h4,h5), pack2bf(h6,h7) };
            uint4 lv = { pack2bf(l0,l1), pack2bf(l2,l3), pack2bf(l4,l5), pack2bf(l6,l7) };
            uint32_t off = swz128((uint32_t)(lr * 128 + ahalf * 64 + j * 16));
            *(uint4*)(bp + off)        = hv;
            *(uint4*)(bp + 2048 + off) = lv;
        }
    };
    auto compute = [&](int c) {
        #pragma unroll
        for (int ks = 0; ks < 4; ks++) {
            // A fragment: m16 x k16 (hi and lo)
            uint32_t ah[4], al_[4];
            {
                int m_loc = lane & 15;
                int kbyte = (ks * 16 + (lane >> 4) * 8) * 2;
                uint32_t off = swz128((uint32_t)(m_loc * 128 + kbyte));
                ldm_x4(ah,  aWarp + off);
                ldm_x4(al_, aWarp + 2048 + off);
            }
            // B fragments: 4 x (n16 x k16) covering this warp's 64 columns
            #pragma unroll
            for (int nf = 0; nf < 4; nf++) {
                int g = lane >> 3, r = lane & 7;
                int n_loc = wn + nf * 16 + ((g & 2) << 2) + r;   // +8 for g>=2
                int kbyte = c * 128 + ks * 32 + (g & 1) * 16;
                uint32_t off = swz512((uint32_t)(n_loc * 512 + kbyte));
                uint32_t th[4], tl[4];
                ldm_x4(th, sb + SB_BH + off);
                ldm_x4(tl, sb + SB_BL + off);
                uint32_t b0h[2] = { th[0], th[1] }, b1h[2] = { th[2], th[3] };
                uint32_t b0l[2] = { tl[0], tl[1] }, b1l[2] = { tl[2], tl[3] };
                mma_bf16(acc[2*nf],   ah,  b0h);
                mma_bf16(acc[2*nf],   al_, b0h);
                mma_bf16(acc[2*nf],   ah,  b0l);
                mma_bf16(acc[2*nf+1], ah,  b1h);
                mma_bf16(acc[2*nf+1], al_, b1h);
                mma_bf16(acc[2*nf+1], ah,  b1l);
            }
        }
    };

    // Single-buffer A pipeline (warp-scoped ordering):
    //   stage(c+1) LDGs fly during compute(c); cvtstore after compute frees
    //   the buffer hazard; __syncwarp orders lane-crossed ldmatrix reads.
    stageA(0);
    cvtstoreA();
    __syncwarp();

    #pragma unroll
    for (int c = 0; c < 4; c++) {
        if (c < 3) stageA(c + 1);
        compute(c);
        if (c < 3) {
            cvtstoreA();
            __syncwarp();
        }
    }

    // Epilogue: direct global stores with bias (bias index = global column)
    #pragma unroll
    for (int n8 = 0; n8 < 8; n8++) {
        int col = bn + wn + n8 * 8 + (lane & 3) * 2;
        int r0  = bm + wm + (lane >> 2);
        float b0 = __ldg(bias + col);
        float b1 = __ldg(bias + col + 1);
        float2 v0 = { acc[n8][0] + b0, acc[n8][1] + b1 };
        float2 v1 = { acc[n8][2] + b0, acc[n8][3] + b1 };
        *(float2*)(C + (size_t)r0 * N + col)       = v0;
        *(float2*)(C + (size_t)(r0 + 8) * N + col) = v1;
    }
}

// ---------------------------------------------------------------------------
// Weight prep: transpose to [N][K] and split into bf16 hi/lo
// ---------------------------------------------------------------------------
__global__ void prep_wsplit(const float* __restrict__ W,        // [256][256]
                            __nv_bfloat16* __restrict__ hi,
                            __nv_bfloat16* __restrict__ lo)
{
    int n = blockIdx.x, k = threadIdx.x;
    float x = W[(size_t)k * 256 + n];
    float hf, lf; bf_split(x, hf, lf);
    hi[(size_t)n * 256 + k] = __float2bfloat16_rn(hf);
    lo[(size_t)n * 256 + k] = __float2bfloat16_rn(lf);
}

__global__ void prep_wcomb(const float* __restrict__ W_off,     // [256][64]
                           const float* __restrict__ W_attn,    // [256][32]
                           const float* __restrict__ b_off,
                           const float* __restrict__ b_attn,
                           __nv_bfloat16* __restrict__ hi,
                           __nv_bfloat16* __restrict__ lo,
                           float* __restrict__ bias)
{
    int n = blockIdx.x, k = threadIdx.x;     // n < 128, k < 256
    float x = 0.f;
    if (n < 64)       x = W_off[(size_t)k * 64 + n];
    else if (n < 96)  x = W_attn[(size_t)k * 32 + (n - 64)];
    float hf, lf; bf_split(x, hf, lf);
    hi[(size_t)n * 256 + k] = __float2bfloat16_rn(hf);
    lo[(size_t)n * 256 + k] = __float2bfloat16_rn(lf);
    if (k == 0) bias[n] = (n < 64) ? b_off[n] : ((n < 96) ? b_attn[n - 64] : 0.f);
}

// ---------------------------------------------------------------------------
// Sample: softmax + bilinear gather, BARRIER-FREE.
// One CTA of 256 threads per (b,q). Warp h = head h, lane = channel.
// ---------------------------------------------------------------------------
__global__ __launch_bounds__(256)
void sample_kernel(const float* __restrict__ refpts)
{
    const int bq = blockIdx.x;
    const int b  = bq / Q_;
    const int t  = threadIdx.x;
    const int h  = t >> 5;
    const int d  = t & 31;

    const float* pr = g_proj + (size_t)bq * PN;

    // attention logits -> softmax (redundant per thread; 4 values)
    float a0 = pr[64 + h * NP + 0];
    float a1 = pr[64 + h * NP + 1];
    float a2 = pr[64 + h * NP + 2];
    float a3 = pr[64 + h * NP + 3];
    float m  = fmaxf(fmaxf(a0, a1), fmaxf(a2, a3));
    float e0 = __expf(a0 - m), e1 = __expf(a1 - m);
    float e2 = __expf(a2 - m), e3 = __expf(a3 - m);
    float inv = 1.f / (e0 + e1 + e2 + e3);
    float wgt[NP] = { e0 * inv, e1 * inv, e2 * inv, e3 * inv };

    const float rx = refpts[(size_t)bq * 2 + 0];
    const float ry = refpts[(size_t)bq * 2 + 1];
    const float* vb = g_values + (size_t)b * HW * D_ + h * DH + d;

    float acc = 0.f;
    #pragma unroll
    for (int p = 0; p < NP; p++) {
        float ox = pr[(h * NP + p) * 2 + 0];
        float oy = pr[(h * NP + p) * 2 + 1];
        float lx = fminf(fmaxf(rx + ox, 0.f), 1.f);
        float ly = fminf(fmaxf(ry + oy, 0.f), 1.f);
        float sx = lx * (float)(Ww - 1);
        float sy = ly * (float)(Hh - 1);
        int x0 = min(max((int)floorf(sx), 0), Ww - 1);
        int y0 = min(max((int)floorf(sy), 0), Hh - 1);
        int x1 = min(x0 + 1, Ww - 1);
        int y1 = min(y0 + 1, Hh - 1);
        float wx1 = sx - (float)x0, wx0 = 1.f - wx1;
        float wy1 = sy - (float)y0, wy0 = 1.f - wy1;

        float g00 = vb[(size_t)(y0 * Ww + x0) * D_];
        float g01 = vb[(size_t)(y1 * Ww + x0) * D_];
        float g10 = vb[(size_t)(y0 * Ww + x1) * D_];
        float g11 = vb[(size_t)(y1 * Ww + x1) * D_];

        float bil = g00 * (wx0 * wy0) + g01 * (wx0 * wy1)
                  + g10 * (wx1 * wy0) + g11 * (wx1 * wy1);
        acc = fmaf(wgt[p], bil, acc);
    }
    g_result[(size_t)bq * D_ + t] = acc;
}

// ---------------------------------------------------------------------------
// kernel_launch
// Inputs: 0=query 1=reference_points 2=input_flatten 3=h 4=w
//   5=W_off 6=b_off 7=W_attn 8=b_attn 9=W_val 10=b_val 11=W_out 12=b_out
// ---------------------------------------------------------------------------
extern "C" void kernel_launch(void* const* d_in, const int* in_sizes, int n_in,
                              void* d_out, int out_size)
{
    const float* query    = (const float*)d_in[0];
    const float* refpts   = (const float*)d_in[1];
    const float* in_flat  = (const float*)d_in[2];
    const float* W_off    = (const float*)d_in[5];
    const float* b_off    = (const float*)d_in[6];
    const float* W_attn   = (const float*)d_in[7];
    const float* b_attn   = (const float*)d_in[8];
    const float* W_val    = (const float*)d_in[9];
    const float* b_val    = (const float*)d_in[10];
    const float* W_out    = (const float*)d_in[11];
    const float* b_out    = (const float*)d_in[12];
    float* out = (float*)d_out;

    float *values_p, *result_p, *proj_p, *biasc_p;
    __nv_bfloat16 *wvh, *wvl, *woh, *wol, *wch, *wcl;
    cudaGetSymbolAddress((void**)&values_p, g_values);
    cudaGetSymbolAddress((void**)&result_p, g_result);
    cudaGetSymbolAddress((void**)&proj_p,   g_proj);
    cudaGetSymbolAddress((void**)&biasc_p,  g_bias_comb);
    cudaGetSymbolAddress((void**)&wvh, g_WvalT_hi);
    cudaGetSymbolAddress((void**)&wvl, g_WvalT_lo);
    cudaGetSymbolAddress((void**)&woh, g_WoutT_hi);
    cudaGetSymbolAddress((void**)&wol, g_WoutT_lo);
    cudaGetSymbolAddress((void**)&wch, g_Wcomb_hi);
    cudaGetSymbolAddress((void**)&wcl, g_Wcomb_lo);

    cudaFuncSetAttribute(gemm_bf16x3, cudaFuncAttributeMaxDynamicSharedMemorySize, SMEM_GEMM);

    // 0) weight prep (tiny)
    prep_wsplit<<<256, 256>>>(W_val, wvh, wvl);
    prep_wsplit<<<256, 256>>>(W_out, woh, wol);
    prep_wcomb<<<128, 256>>>(W_off, W_attn, b_off, b_attn, wch, wcl, biasc_p);

    // 1) projections: g_proj[16384,128] = query @ Wcomb^T + bias_comb
    {
        dim3 grid(BQ / 128, 1);
        gemm_bf16x3<<<grid, 512, SMEM_GEMM>>>(query, wch, wcl, biasc_p, proj_p, PN);
    }

    // 2) values: g_values[80000,256] = input_flatten @ W_val + b_val
    {
        dim3 grid((B_ * HW) / 128, 2);
        gemm_bf16x3<<<grid, 512, SMEM_GEMM>>>(in_flat, wvh, wvl, b_val, values_p, D_);
    }

    // 3) softmax + bilinear sampling (barrier-free) -> g_result[16384,256]
    sample_kernel<<<BQ, 256>>>(refpts);

    // 4) out = g_result @ W_out + b_out
    {
        dim3 grid(BQ / 128, 2);
        gemm_bf16x3<<<grid, 512, SMEM_GEMM>>>(result_p, woh, wol, b_out, out, D_);
    }
}